// round 9
// baseline (speedup 1.0000x reference)
#include <cuda_runtime.h>
#include <cuda_bf16.h>
#include <cstdint>

// SIR SDE: 8192 trajectories x 4900 effective steps, sampled every 100 steps (49 samples),
// features: max, (argmax+u)/49, std(diff(log x)).
//
// R9 = R8 (139us: 128 blocks x 64 thr, per-warp cp.async 3-buffer pipeline, burst LDS,
// tail drain, q = rec*s, z = i/DT) + ONE delta: the sqrt is software-pipelined one step
// ahead. sq = sqrt(|r0|) is loop-carried state, recomputed IMMEDIATELY after the r0
// update, so under in-order issue the MUFU starts the moment r0 lands instead of ~8 cyc
// later behind the off-chain FFMAs. Chain/step: FFMA(4) + MUFU(16) [= 20-24 cyc] with all
// other work in the MUFU shadow. Bitwise-identical math to R8.

#define BSZ    8192
#define CH     20            // steps per chunk; 100 % CH == 0
#define NCHUNK 245           // 4900 effective steps
#define WPB    2             // warps per block
#define THREADS (WPB * 32)

__device__ __forceinline__ void cp_async16(uint32_t saddr, const void* gptr) {
    asm volatile("cp.async.ca.shared.global [%0], [%1], 16;" :: "r"(saddr), "l"(gptr));
}
__device__ __forceinline__ void cp_commit() {
    asm volatile("cp.async.commit_group;");
}
template <int N>
__device__ __forceinline__ void cp_wait() {
    asm volatile("cp.async.wait_group %0;" :: "n"(N));
}
__device__ __forceinline__ float sqrt_approx(float x) {
    float r;
    asm("sqrt.approx.f32 %0, %1;" : "=f"(r) : "f"(x));
    return r;
}

__global__ __launch_bounds__(THREADS, 1)
void sir_sde_kernel(const float* __restrict__ cond,
                    const float* __restrict__ dW,
                    const float* __restrict__ u,
                    float* __restrict__ out)
{
    __shared__ float sdw[WPB][3 * CH * 32];   // per-warp: 3 bufs x 20 steps x 32 lanes

    const int lane = threadIdx.x & 31;
    const int w    = threadIdx.x >> 5;
    const int b0   = blockIdx.x * THREADS + w * 32;   // first trajectory of this warp
    const int b    = b0 + lane;

    // ---------- per-trajectory parameters ----------
    const float inf_rate = cond[b * 4 + 0];
    const float rec      = cond[b * 4 + 1];
    const float mr       = cond[b * 4 + 2];
    const float vol      = cond[b * 4 + 3];

    const float DT      = 0.01f;
    const float r0_init = __fdiv_rn(inf_rate, rec);
    const float sdt     = sqrtf(DT);
    const float dtmr    = DT * mr;
    const float om      = 1.0f - dtmr;        // r0' = om*r0 + c1 + sq*c2
    const float c1      = dtmr * r0_init;
    const float kvol    = vol * sdt;
    const float ndtrec  = -DT * rec;          // q' = q + ndtrec*ni
    const float omr     = 1.0f + ndtrec;      // z' = omr*z + ni   (z = i/DT)

    // ---------- state (s -> q = rec*s, i -> z = i/DT; sq pipelined one step ahead) ----------
    float q  = rec * 0.99f;
    float z  = 1.0f;                          // i0 = 0.01 = DT*1
    float r0 = r0_init;
    float sq = sqrt_approx(fabsf(r0));        // sq always holds sqrt(|current r0|)

    // ---------- feature accumulators ----------
    float cur_max = -3.402823466e38f;
    int   cur_arg = 0;
    float prev_lg = 0.0f;
    float sumd = 0.0f, sumd2 = 0.0f;

    // ---------- cp.async chunk copier (per warp, self-contained) ----------
    uint32_t smem_base;
    asm("{ .reg .u64 t; cvta.to.shared.u64 t, %1; cvt.u32.u64 %0, t; }"
        : "=r"(smem_base) : "l"(&sdw[w][0]));

    const char* gbase = (const char*)(dW + b0);

    auto issue_chunk = [&](int c, int bufidx) {
        const char* g = gbase + (size_t)c * CH * BSZ * 4;
        uint32_t sb = smem_base + bufidx * (CH * 128);
#pragma unroll
        for (int i = 0; i < 5; ++i) {
            int f   = i * 512 + lane * 16;      // flat byte offset in this warp's buffer
            int row = f >> 7;                   // /128
            int col = f & 127;
            cp_async16(sb + f, g + (size_t)row * BSZ * 4 + col);
        }
        cp_commit();
    };

    // prologue: chunks 0,1 in flight
    issue_chunk(0, 0);
    issue_chunk(1, 1);

    const float* sbuf = &sdw[w][0];

#pragma unroll 1
    for (int c = 0; c < NCHUNK; ++c) {
        // Tail: fewer than 2 groups pending -> wait<1> would not cover chunk c. Full drain.
        if (c >= NCHUNK - 2) cp_wait<0>();
        else                 cp_wait<1>();
        __syncwarp();

        // burst-copy chunk c to registers (conflict-free LDS)
        float dwv[CH];
        const float* sp = sbuf + (c % 3) * (CH * 32) + lane;
#pragma unroll
        for (int k = 0; k < CH; ++k) dwv[k] = sp[k * 32];

        // refill chunk c+2 into buffer (c+2)%3 (last consumer finished a chunk ago)
        if (c + 2 < NCHUNK) issue_chunk(c + 2, (c + 2) % 3);

        // ---------- 20 Euler-Maruyama steps (sqrt rotated to chain head) ----------
#pragma unroll
        for (int k = 0; k < CH; ++k) {
            const float c2 = dwv[k] * kvol;     // shadow
            const float ni = r0 * q;            // shadow (old r0)
            const float t  = fmaf(r0, om, c1);  // shadow
            r0 = fmaf(sq, c2, t);               // chain: FFMA
            sq = sqrt_approx(fabsf(r0));        // chain: MUFU, issued right after r0 lands
            q  = fmaf(ni, ndtrec, q);           // shadow
            z  = fmaf(omr, z, ni);              // shadow
        }

        // ---------- sample after steps 99, 199, ..., 4899 ----------
        if (c % 5 == 4) {
            const int j = c / 5;
            float x = DT * z;                   // i = DT*z
            if ((__float_as_uint(x) & 0x7f800000u) == 0x7f800000u) x = 0.0f; // nan/inf -> 0
            x = fmaxf(x, 1e-5f);

            if (x > cur_max) { cur_max = x; cur_arg = j; }
            const float lg = logf(x);
            if (j > 0) {
                const float d = lg - prev_lg;
                sumd  += d;
                sumd2 += d * d;
            }
            prev_lg = lg;
        }
    }

    // ---------- features ----------
    const float max_at = ((float)cur_arg + u[b]) / 49.0f;
    const float mean   = sumd * (1.0f / 48.0f);
    float var = sumd2 * (1.0f / 48.0f) - mean * mean;   // ddof=0
    var = fmaxf(var, 0.0f);

    out[b * 3 + 0] = cur_max;
    out[b * 3 + 1] = max_at;
    out[b * 3 + 2] = sqrtf(var);
}

extern "C" void kernel_launch(void* const* d_in, const int* in_sizes, int n_in,
                              void* d_out, int out_size)
{
    const float* cond = (const float*)d_in[0];   // (8192, 4)
    const float* dW   = (const float*)d_in[1];   // (5000, 8192)
    const float* u    = (const float*)d_in[2];   // (8192,)
    float* out        = (float*)d_out;           // (8192, 3)

    sir_sde_kernel<<<BSZ / THREADS, THREADS>>>(cond, dW, u, out);
}